// round 9
// baseline (speedup 1.0000x reference)
#include <cuda_runtime.h>

// GADBase guided anisotropic diffusion — fully register-resident persistent kernel.
// 128 CTAs (tile 128x128, 512 threads, 1 CTA/SM guaranteed). Each thread owns an
// 8-row x 4-col strip: image v[8], vertical conds a[9], horizontal conds cr[8]
// all in registers for all 64 iterations. Warp = one 8x8-block row -> shfl-only
// ratio reduction. Inter-warp rows via 2-row SMEM exchange; inter-CTA via global
// rings + acquire-spin flags.

#define NPIX   (1024*1024)
#define CV_OFF 2097152
#define CH_OFF 4192256
#define GXT 8
#define GYT 8
#define NCTA (2*GXT*GYT)        // 128

__device__ float g_shift;
__device__ int   g_flag[NCTA];
__device__ float g_brow[2][2][GYT][2][1024];   // [parity][batch][tyr][top/bot][col]
__device__ float g_bcol[2][2][GXT][2][1024];   // [parity][batch][bx][left/right][row]

// ---------------------------------------------------------------------------
__global__ void k_pre(const float* __restrict__ src)
{
    __shared__ float red[32];
    int tid = threadIdx.x;                       // 1024 threads
    float mn = 1e30f;
    for (int i = tid; i < 2*128*128; i += 1024) mn = fminf(mn, src[i]);
    #pragma unroll
    for (int o = 16; o; o >>= 1) mn = fminf(mn, __shfl_xor_sync(~0u, mn, o));
    if ((tid & 31) == 0) red[tid >> 5] = mn;
    __syncthreads();
    if (tid < 32) {
        float v = red[tid];
        #pragma unroll
        for (int o = 16; o; o >>= 1) v = fminf(v, __shfl_xor_sync(~0u, v, o));
        if (tid == 0) g_shift = (v <= 0.1f) ? 0.1f : 0.0f;
    }
    if (tid < NCTA) g_flag[tid] = -1;
}

// ---------------------------------------------------------------------------
__device__ __forceinline__ void spin_ge(const int* p, int t)
{
    int v;
    do {
        asm volatile("ld.acquire.gpu.global.s32 %0, [%1];"
                     : "=r"(v) : "l"(p) : "memory");
    } while (v < t);
}

__global__ void __launch_bounds__(512, 1)
k_diffuse(const float* __restrict__ guide, const float* __restrict__ y,
          const float* __restrict__ src,   const float* __restrict__ mask,
          float* __restrict__ out)
{
    __shared__ float s_bt[16][2][128];   // per-warp top/bottom rows
    __shared__ float s_clw[128];         // 0.24*ch at col colbase-1, per row
    __shared__ float s_src[256];
    __shared__ float s_msk[256];

    const int tid  = threadIdx.x;
    const int w    = tid >> 5, lane = tid & 31;
    const int bx = blockIdx.x, tyr = blockIdx.y, b = blockIdx.z;
    const int colbase = bx*128, rowbase = tyr*128;
    const int c0 = lane*4, r0 = w*8;
    const int gc0 = colbase + c0, gr0 = rowbase + r0;
    const int cid = (b*GYT + tyr)*GXT + bx;
    const float shift = g_shift;
    const float K2 = 0.03f*0.03f;

    float4 v[8], a[9], cr[8];

    // ======================= prologue: conductances + init =================
    const float* G0 = guide + b*3*NPIX;
    const float* G1 = G0 + NPIX;
    const float* G2 = G1 + NPIX;
    const float* Yp = y + b*NPIX;

    float4 p0 = {0,0,0,0}, p1 = {0,0,0,0}, p2 = {0,0,0,0}, py = {0,0,0,0};
    #pragma unroll
    for (int j = 0; j < 10; j++) {
        int row = gr0 - 1 + j;
        float4 q0 = {0,0,0,0}, q1 = {0,0,0,0}, q2 = {0,0,0,0}, qy = {0,0,0,0};
        bool inr = (unsigned)row < 1024u;
        int off = row*1024 + gc0;
        if (inr) {
            q0 = *(const float4*)(G0 + off);
            q1 = *(const float4*)(G1 + off);
            q2 = *(const float4*)(G2 + off);
            qy = *(const float4*)(Yp + off);
        }
        if (j >= 1) {
            int brow = row - 1;                         // vertical boundary row
            float4 cv4 = {0,0,0,0};
            if ((unsigned)brow < 1023u) {
                float sx = 0.25f*(fabsf(q0.x-p0.x)+fabsf(q1.x-p1.x)+fabsf(q2.x-p2.x)+fabsf(qy.x-py.x));
                float sy = 0.25f*(fabsf(q0.y-p0.y)+fabsf(q1.y-p1.y)+fabsf(q2.y-p2.y)+fabsf(qy.y-py.y));
                float sz = 0.25f*(fabsf(q0.z-p0.z)+fabsf(q1.z-p1.z)+fabsf(q2.z-p2.z)+fabsf(qy.z-py.z));
                float sw = 0.25f*(fabsf(q0.w-p0.w)+fabsf(q1.w-p1.w)+fabsf(q2.w-p2.w)+fabsf(qy.w-py.w));
                cv4.x = 1.f/(1.f + sx*sx/K2);
                cv4.y = 1.f/(1.f + sy*sy/K2);
                cv4.z = 1.f/(1.f + sz*sz/K2);
                cv4.w = 1.f/(1.f + sw*sw/K2);
                if (j >= 2)                            // brow in [gr0, gr0+7]
                    *(float4*)(out + CV_OFF + b*(1023*1024) + brow*1024 + gc0) = cv4;
            }
            a[j-1] = make_float4(0.24f*cv4.x, 0.24f*cv4.y, 0.24f*cv4.z, 0.24f*cv4.w);
        }
        if (inr && j >= 1 && j <= 8) {
            int i = j - 1;                              // interior row gr0+i
            v[i] = make_float4(qy.x+shift, qy.y+shift, qy.z+shift, qy.w+shift);
            float r0s = 0.f, r1s = 0.f, r2s = 0.f, rys = 0.f;
            if (gc0 + 4 < 1024) {
                r0s = G0[off+4]; r1s = G1[off+4]; r2s = G2[off+4]; rys = Yp[off+4];
            }
            float sx = 0.25f*(fabsf(q0.y-q0.x)+fabsf(q1.y-q1.x)+fabsf(q2.y-q2.x)+fabsf(qy.y-qy.x));
            float sy = 0.25f*(fabsf(q0.z-q0.y)+fabsf(q1.z-q1.y)+fabsf(q2.z-q2.y)+fabsf(qy.z-qy.y));
            float sz = 0.25f*(fabsf(q0.w-q0.z)+fabsf(q1.w-q1.z)+fabsf(q2.w-q2.z)+fabsf(qy.w-qy.z));
            float sw = 0.25f*(fabsf(r0s-q0.w)+fabsf(r1s-q1.w)+fabsf(r2s-q2.w)+fabsf(rys-qy.w));
            float chx = 1.f/(1.f + sx*sx/K2);
            float chy = 1.f/(1.f + sy*sy/K2);
            float chz = 1.f/(1.f + sz*sz/K2);
            float chw = (gc0 + 3 < 1023) ? 1.f/(1.f + sw*sw/K2) : 0.f;
            float* cho = out + CH_OFF + b*(1024*1023) + row*1023 + gc0;
            cho[0] = chx; cho[1] = chy; cho[2] = chz;
            if (gc0 + 3 < 1023) cho[3] = chw;
            cr[i] = make_float4(0.24f*chx, 0.24f*chy, 0.24f*chz, 0.24f*chw);
            if (lane == 0) {
                float val = 0.f;
                if (bx > 0) {
                    float l0 = G0[off-1], l1 = G1[off-1], l2 = G2[off-1], ly = Yp[off-1];
                    float s = 0.25f*(fabsf(q0.x-l0)+fabsf(q1.x-l1)+fabsf(q2.x-l2)+fabsf(qy.x-ly));
                    val = 0.24f/(1.f + s*s/K2);
                }
                s_clw[r0 + i] = val;
            }
        }
        p0 = q0; p1 = q1; p2 = q2; py = qy;
    }

    if (tid < 256) {
        int bi = b*16384 + (tyr*16 + (tid >> 4))*128 + bx*16 + (tid & 15);
        s_src[tid] = src[bi] + shift;
        s_msk[tid] = (mask[bi] < 0.5f) ? 0.f : 1.f;
    }

    // publish state-0 boundaries
    *(float4*)&s_bt[w][0][c0] = v[0];
    *(float4*)&s_bt[w][1][c0] = v[7];
    if (w == 0  && tyr > 0)       *(float4*)&g_brow[0][b][tyr][0][gc0] = v[0];
    if (w == 15 && tyr < GYT - 1) *(float4*)&g_brow[0][b][tyr][1][gc0] = v[7];
    if (lane == 0 && bx > 0) {
        #pragma unroll
        for (int i = 0; i < 8; i++) g_bcol[0][b][bx][0][rowbase + r0 + i] = v[i].x;
    }
    if (lane == 31 && bx < GXT - 1) {
        #pragma unroll
        for (int i = 0; i < 8; i++) g_bcol[0][b][bx][1][rowbase + r0 + i] = v[i].w;
    }
    __syncthreads();
    if (tid == 0) { __threadfence(); atomicExch(&g_flag[cid], 0); }

    // ======================= 64 diffusion iterations =======================
    const bool hw = (bx > 0), he = (bx < GXT - 1);
    for (int t = 0; t < 64; t++) {
        int par = t & 1;
        float4 up, dn;
        if (w == 0) {
            if (tyr > 0) {
                spin_ge(&g_flag[cid - GXT], t);
                up = __ldcg((const float4*)&g_brow[par][b][tyr-1][1][gc0]);
            } else up = make_float4(0,0,0,0);
        } else up = *(const float4*)&s_bt[w-1][1][c0];
        if (w == 15) {
            if (tyr < GYT - 1) {
                spin_ge(&g_flag[cid + GXT], t);
                dn = __ldcg((const float4*)&g_brow[par][b][tyr+1][0][gc0]);
            } else dn = make_float4(0,0,0,0);
        } else dn = *(const float4*)&s_bt[w+1][0][c0];
        if (hw) spin_ge(&g_flag[cid - 1], t);
        if (he) spin_ge(&g_flag[cid + 1], t);
        __syncthreads();                       // boundary reads done before writes

        const float* wr = &g_bcol[par][b][hw ? bx-1 : 0][1][rowbase + r0];
        const float* er = &g_bcol[par][b][he ? bx+1 : 0][0][rowbase + r0];

        float4 pv = up;
        float acc = 0.f;
        #pragma unroll
        for (int i = 0; i < 8; i++) {
            float4 cur  = v[i];
            float4 down = (i < 7) ? v[i+1] : dn;
            float lf = __shfl_up_sync(0xffffffffu, cur.w, 1);
            if (lane == 0)  lf = hw ? __ldcg(wr + i) : 0.f;
            float rt = __shfl_down_sync(0xffffffffu, cur.x, 1);
            if (lane == 31) rt = he ? __ldcg(er + i) : 0.f;
            float cl = __shfl_up_sync(0xffffffffu, cr[i].w, 1);
            if (lane == 0)  cl = s_clw[r0 + i];
            float4 a0 = a[i], a1 = a[i+1], c = cr[i];
            float nx = cur.x + a1.x*(down.x-cur.x) - a0.x*(cur.x-pv.x) + c.x*(cur.y-cur.x) - cl *(cur.x-lf);
            float ny = cur.y + a1.y*(down.y-cur.y) - a0.y*(cur.y-pv.y) + c.y*(cur.z-cur.y) - c.x*(cur.y-cur.x);
            float nz = cur.z + a1.z*(down.z-cur.z) - a0.z*(cur.z-pv.z) + c.z*(cur.w-cur.z) - c.y*(cur.z-cur.y);
            float nw = cur.w + a1.w*(down.w-cur.w) - a0.w*(cur.w-pv.w) + c.w*(rt   -cur.w) - c.z*(cur.w-cur.z);
            pv = cur;
            v[i] = make_float4(nx, ny, nz, nw);
            acc += (nx + ny) + (nz + nw);
        }

        // 8x8 block sum: warp covers one block row; block = 2 adjacent lanes
        float bsum = acc + __shfl_xor_sync(0xffffffffu, acc, 1);
        int blk = w*16 + (lane >> 1);
        float ratio = (s_msk[blk] != 0.f)
                    ? s_src[blk] / (bsum*(1.f/64.f) + 1e-8f) : 1.f;
        #pragma unroll
        for (int i = 0; i < 8; i++) {
            v[i].x *= ratio; v[i].y *= ratio; v[i].z *= ratio; v[i].w *= ratio;
        }

        if (t == 63) break;

        // publish state t+1 boundaries
        *(float4*)&s_bt[w][0][c0] = v[0];
        *(float4*)&s_bt[w][1][c0] = v[7];
        int pn = (t + 1) & 1;
        if (w == 0  && tyr > 0)       __stcg((float4*)&g_brow[pn][b][tyr][0][gc0], v[0]);
        if (w == 15 && tyr < GYT - 1) __stcg((float4*)&g_brow[pn][b][tyr][1][gc0], v[7]);
        if (lane == 0 && hw) {
            #pragma unroll
            for (int i = 0; i < 8; i++)
                __stcg(&g_bcol[pn][b][bx][0][rowbase + r0 + i], v[i].x);
        }
        if (lane == 31 && he) {
            #pragma unroll
            for (int i = 0; i < 8; i++)
                __stcg(&g_bcol[pn][b][bx][1][rowbase + r0 + i], v[i].w);
        }
        __syncthreads();                       // all publishes visible in CTA
        if (tid == 0) { __threadfence(); atomicExch(&g_flag[cid], t + 1); }
    }

    // ======================= epilogue ======================================
    #pragma unroll
    for (int i = 0; i < 8; i++) {
        float4 o = make_float4(v[i].x - shift, v[i].y - shift,
                               v[i].z - shift, v[i].w - shift);
        *(float4*)(out + b*NPIX + (gr0 + i)*1024 + gc0) = o;
    }
}

// ---------------------------------------------------------------------------
extern "C" void kernel_launch(void* const* d_in, const int* in_sizes, int n_in,
                              void* d_out, int out_size)
{
    const float* guide = (const float*)d_in[0];
    const float* y     = (const float*)d_in[1];
    const float* src   = (const float*)d_in[2];
    const float* mask  = (const float*)d_in[3];
    float* out = (float*)d_out;

    k_pre<<<1, 1024>>>(src);
    dim3 g(GXT, GYT, 2);                        // 128 CTAs — 1/SM, all resident
    k_diffuse<<<g, 512>>>(guide, y, src, mask, out);
}